// round 1
// baseline (speedup 1.0000x reference)
#include <cuda_runtime.h>

#define Bx 4
#define Lx 512
#define Dx 128

// Scratch (static device arrays: allowed; no allocations anywhere)
__device__ float g_Q[Bx * Lx * Dx];
__device__ float g_K[Bx * Lx * Dx];
__device__ float g_S[(size_t)Bx * Lx * Lx];

__device__ __forceinline__ float tanh_fast(float v) {
    float y;
    asm("tanh.approx.f32 %0, %1;" : "=f"(y) : "f"(v));
    return y;
}

// ---------------------------------------------------------------------------
// Kernel 1: Q = x @ Wq^T + bq ; K = x @ Wk^T + bk
// Block: 256 threads. threads 0..127 -> Q (e = tid), 128..255 -> K.
// Each block handles 16 rows of x (staged in shared), thread computes column e
// for all 16 rows with W row streamed as float4 (L1/L2 resident).
// ---------------------------------------------------------------------------
__global__ void qk_kernel(const float* __restrict__ x,
                          const float* __restrict__ Wq, const float* __restrict__ bq,
                          const float* __restrict__ Wk, const float* __restrict__ bk) {
    __shared__ float4 xs[16][32];
    int row0 = blockIdx.x * 16;
    int e = threadIdx.x & 127;
    int which = threadIdx.x >> 7;

    const float4* x4 = (const float4*)(x + (size_t)row0 * Dx);
    for (int t = threadIdx.x; t < 16 * 32; t += 256)
        ((float4*)xs)[t] = x4[t];
    __syncthreads();

    const float* W = which ? Wk : Wq;
    float bias = which ? bk[e] : bq[e];
    const float4* W4 = (const float4*)(W + (size_t)e * Dx);

    float acc[16];
#pragma unroll
    for (int r = 0; r < 16; r++) acc[r] = 0.f;

#pragma unroll 4
    for (int d4 = 0; d4 < 32; d4++) {
        float4 wv = __ldg(&W4[d4]);
#pragma unroll
        for (int r = 0; r < 16; r++) {
            float4 xv = xs[r][d4];
            acc[r] += wv.x * xv.x + wv.y * xv.y + wv.z * xv.z + wv.w * xv.w;
        }
    }

    float* o = which ? g_K : g_Q;
#pragma unroll
    for (int r = 0; r < 16; r++)
        o[(size_t)(row0 + r) * Dx + e] = acc[r] + bias;
}

// ---------------------------------------------------------------------------
// Kernel 2: S[b,i,j] = sum_d w[d]*tanh(Q[b,i,d]+K[b,j,d]) + bw
// Grid (L/32, L/32, B), 256 threads (16x16), 2x2 register tile per thread.
// Q/K staged in shared transposed [d][row] with +1 pad (conflict-free).
// MUFU (tanh.approx) bound by design.
// ---------------------------------------------------------------------------
__global__ void score_kernel(const float* __restrict__ w, const float* __restrict__ bw) {
    __shared__ float Qs[32][33];
    __shared__ float Ks[32][33];
    __shared__ float ws[Dx];

    int b = blockIdx.z;
    int i0 = blockIdx.y * 32;
    int j0 = blockIdx.x * 32;
    int tx = threadIdx.x & 15;
    int ty = threadIdx.x >> 4;

    if (threadIdx.x < Dx) ws[threadIdx.x] = w[threadIdx.x];

    const float* Qb = g_Q + (size_t)b * Lx * Dx;
    const float* Kb = g_K + (size_t)b * Lx * Dx;
    int dd0 = threadIdx.x & 31;
    int rb = threadIdx.x >> 5;

    float a00 = 0.f, a01 = 0.f, a10 = 0.f, a11 = 0.f;

    for (int dc = 0; dc < Dx; dc += 32) {
        __syncthreads();  // also covers ws on first pass; protects reuse after
#pragma unroll
        for (int p = 0; p < 4; p++) {
            int r = rb + p * 8;
            Qs[dd0][r] = Qb[(size_t)(i0 + r) * Dx + dc + dd0];
            Ks[dd0][r] = Kb[(size_t)(j0 + r) * Dx + dc + dd0];
        }
        __syncthreads();
#pragma unroll
        for (int dd = 0; dd < 32; dd++) {
            float wv = ws[dc + dd];
            float q0 = Qs[dd][ty];
            float q1 = Qs[dd][ty + 16];
            float k0 = Ks[dd][tx];
            float k1 = Ks[dd][tx + 16];
            a00 += wv * tanh_fast(q0 + k0);
            a01 += wv * tanh_fast(q0 + k1);
            a10 += wv * tanh_fast(q1 + k0);
            a11 += wv * tanh_fast(q1 + k1);
        }
    }

    float bwv = bw[0];
    float* Sb = g_S + ((size_t)b * Lx + i0) * Lx + j0;
    Sb[(size_t)ty * Lx + tx]              = a00 + bwv;
    Sb[(size_t)ty * Lx + tx + 16]         = a01 + bwv;
    Sb[(size_t)(ty + 16) * Lx + tx]       = a10 + bwv;
    Sb[(size_t)(ty + 16) * Lx + tx + 16]  = a11 + bwv;
}

// ---------------------------------------------------------------------------
// Kernel 3: softmax over j + out = attn @ x
// Block: 256 threads handles 16 query rows. S tile -> shared, warp computes
// softmax for 2 rows, then register-tiled P @ X (thread owns one d column for
// 8 rows; P read as broadcast float4 from shared).
// ---------------------------------------------------------------------------
__global__ void out_kernel(const float* __restrict__ x, float* __restrict__ out) {
    __shared__ float Ps[16][Lx];   // 32 KB
    __shared__ float linv[16];

    int row0 = blockIdx.x * 16;        // global row in [0, B*L)
    int bb = row0 >> 9;                // / L

    const float4* S4 = (const float4*)(g_S + (size_t)row0 * Lx);
    for (int t = threadIdx.x; t < 16 * Lx / 4; t += 256)
        ((float4*)Ps)[t] = S4[t];
    __syncthreads();

    int warp = threadIdx.x >> 5;
    int lane = threadIdx.x & 31;

#pragma unroll
    for (int rr = 0; rr < 2; rr++) {
        int r = warp * 2 + rr;
        float v[16];
        float m = -1e30f;
#pragma unroll
        for (int c = 0; c < 16; c++) {
            v[c] = Ps[r][lane + c * 32];
            m = fmaxf(m, v[c]);
        }
#pragma unroll
        for (int o = 16; o; o >>= 1) m = fmaxf(m, __shfl_xor_sync(0xffffffffu, m, o));
        float s = 0.f;
#pragma unroll
        for (int c = 0; c < 16; c++) {
            float e = exp2f((v[c] - m) * 1.4426950408889634f);
            s += e;
            Ps[r][lane + c * 32] = e;
        }
#pragma unroll
        for (int o = 16; o; o >>= 1) s += __shfl_xor_sync(0xffffffffu, s, o);
        if (lane == 0) linv[r] = 1.0f / s;
    }
    __syncthreads();

    int d = threadIdx.x & 127;
    int ig = threadIdx.x >> 7;   // 0 -> rows 0..7, 1 -> rows 8..15
    const float* xb = x + (size_t)bb * Lx * Dx;

    float acc[8];
#pragma unroll
    for (int r = 0; r < 8; r++) acc[r] = 0.f;

    for (int j = 0; j < Lx; j += 4) {
        float xv0 = xb[(size_t)(j + 0) * Dx + d];
        float xv1 = xb[(size_t)(j + 1) * Dx + d];
        float xv2 = xb[(size_t)(j + 2) * Dx + d];
        float xv3 = xb[(size_t)(j + 3) * Dx + d];
#pragma unroll
        for (int r = 0; r < 8; r++) {
            float4 p = *(const float4*)&Ps[ig * 8 + r][j];
            acc[r] += p.x * xv0 + p.y * xv1 + p.z * xv2 + p.w * xv3;
        }
    }

#pragma unroll
    for (int r = 0; r < 8; r++) {
        int row = row0 + ig * 8 + r;
        out[(size_t)row * Dx + d] = acc[r] * linv[ig * 8 + r];
    }
}

// ---------------------------------------------------------------------------
extern "C" void kernel_launch(void* const* d_in, const int* in_sizes, int n_in,
                              void* d_out, int out_size) {
    const float* x  = (const float*)d_in[0];
    // d_in[1] = mask (bool) — intentionally unused: reference's masked_fill is
    // out-of-place and discarded, so mask has no effect on the output.
    const float* Wq = (const float*)d_in[2];
    const float* bq = (const float*)d_in[3];
    const float* Wk = (const float*)d_in[4];
    const float* bk = (const float*)d_in[5];
    const float* w  = (const float*)d_in[6];
    const float* bw = (const float*)d_in[7];
    float* out = (float*)d_out;

    qk_kernel<<<Bx * Lx / 16, 256>>>(x, Wq, bq, Wk, bk);

    dim3 g2(Lx / 32, Lx / 32, Bx);
    score_kernel<<<g2, 256>>>(w, bw);

    out_kernel<<<Bx * Lx / 16, 256>>>(x, out);
}